// round 1
// baseline (speedup 1.0000x reference)
#include <cuda_runtime.h>

#define G_ 4
#define T_ 2048
#define E_ 8
#define D_ 1024
#define C_ 2048

// probs scratch, expert-major: g_probs[(g*E + e)*T + t]
__device__ float  g_probs[G_ * E_ * T_];
__device__ double g_zacc;

// ---------------------------------------------------------------------------
// Kernel 1: zero the whole output (1.07 GB) + reset z accumulator.
// Pure store-bandwidth kernel: float4 grid-stride.
// ---------------------------------------------------------------------------
__global__ void zero_kernel(float* __restrict__ out, long long n) {
    long long n4 = n >> 2;
    float4* o4 = reinterpret_cast<float4*>(out);
    long long stride = (long long)gridDim.x * blockDim.x;
    float4 z = make_float4(0.f, 0.f, 0.f, 0.f);
    for (long long i = (long long)blockIdx.x * blockDim.x + threadIdx.x; i < n4; i += stride)
        o4[i] = z;
    if (blockIdx.x == 0 && threadIdx.x == 0) {
        for (long long i = (n4 << 2); i < n; ++i) out[i] = 0.f;
        g_zacc = 0.0;
    }
}

// ---------------------------------------------------------------------------
// Kernel 2: per-token router logits -> softmax probs + z-loss partial.
// One block per token (G*T blocks, 256 threads). Warp w handles expert w.
// W (32 KB) stays L2-resident; x row (4 KB) L1-resident across 8 warps.
// ---------------------------------------------------------------------------
__global__ void router_kernel(const float* __restrict__ x,
                              const float* __restrict__ W,
                              const float* __restrict__ b) {
    int token = blockIdx.x;            // 0 .. G*T-1
    int g = token / T_;
    int t = token % T_;
    int warp = threadIdx.x >> 5;       // expert index (8 warps)
    int lane = threadIdx.x & 31;

    const float* xrow = x + (long long)token * D_;
    const float* wrow = W + warp * D_;

    float acc = 0.f;
    #pragma unroll 8
    for (int d = lane; d < D_; d += 32)
        acc += xrow[d] * wrow[d];
    #pragma unroll
    for (int o = 16; o > 0; o >>= 1)
        acc += __shfl_xor_sync(0xffffffffu, acc, o);

    __shared__ float logits[E_];
    if (lane == 0) logits[warp] = acc + b[warp];
    __syncthreads();

    if (threadIdx.x == 0) {
        float m = -1e30f;
        #pragma unroll
        for (int e = 0; e < E_; e++) m = fmaxf(m, logits[e]);
        float ex[E_];
        float s = 0.f;
        #pragma unroll
        for (int e = 0; e < E_; e++) { ex[e] = expf(logits[e] - m); s += ex[e]; }
        float inv = 1.f / s;
        float lse = m + logf(s);
        float zt = 0.f;
        #pragma unroll
        for (int e = 0; e < E_; e++) {
            g_probs[((g * E_) + e) * T_ + t] = ex[e] * inv;
            float ls = logits[e] - lse;
            zt += ls * ls;
        }
        atomicAdd(&g_zacc, (double)zt);
    }
}

// ---------------------------------------------------------------------------
// Kernel 3: per-(g,e) top-cap over T=2048 tokens via in-shared bitonic sort
// of packed keys (prob_bits << 32) | ~idx  -> descending sort gives
// prob desc, index asc on ties (matches jax.lax.top_k). Then scatter the
// nonzeros into dispatch/combine.
// ---------------------------------------------------------------------------
__global__ void topk_kernel(float* __restrict__ out) {
    __shared__ unsigned long long s[T_];   // 16 KB

    int g = blockIdx.x / E_;
    int e = blockIdx.x % E_;

    const float* p = g_probs + (long long)(g * E_ + e) * T_;
    for (int t = threadIdx.x; t < T_; t += blockDim.x) {
        unsigned int pb = __float_as_uint(p[t]);   // probs > 0 -> bits monotonic
        s[t] = ((unsigned long long)pb << 32) | (unsigned int)(~t);
    }
    __syncthreads();

    // Bitonic sort, full descending.
    for (int k = 2; k <= T_; k <<= 1) {
        for (int j = k >> 1; j > 0; j >>= 1) {
            for (int i = threadIdx.x; i < T_; i += blockDim.x) {
                int ixj = i ^ j;
                if (ixj > i) {
                    bool desc = ((i & k) == 0);
                    unsigned long long a = s[i], c = s[ixj];
                    if (desc ? (a < c) : (a > c)) { s[i] = c; s[ixj] = a; }
                }
            }
            __syncthreads();
        }
    }

    const int caps[E_] = {512, 512, 256, 256, 128, 128, 128, 128};
    int cap = caps[e];
    const long long NTOT = (long long)G_ * T_ * E_ * C_;

    for (int r = threadIdx.x; r < cap; r += blockDim.x) {
        unsigned long long key = s[r];
        float gate = __uint_as_float((unsigned int)(key >> 32));
        int tok = (int)(~(unsigned int)(key & 0xffffffffu));
        long long off = ((((long long)g * T_ + tok) * E_ + e) * C_ + r);
        out[off]        = 1.0f;   // dispatch_mask
        out[NTOT + off] = gate;   // combine_array
    }
}

// ---------------------------------------------------------------------------
// Kernel 4: write z-loss scalar (last output element).
// ---------------------------------------------------------------------------
__global__ void zloss_kernel(float* __restrict__ out, long long n) {
    out[n - 1] = (float)(g_zacc / (double)(G_ * T_ * E_));
}

extern "C" void kernel_launch(void* const* d_in, const int* in_sizes, int n_in,
                              void* d_out, int out_size) {
    const float* x = (const float*)d_in[0];   // token_inputs [G,T,D]
    const float* W = (const float*)d_in[1];   // [E,D]
    const float* b = (const float*)d_in[2];   // [E]
    float* out = (float*)d_out;
    long long n = (long long)out_size;

    zero_kernel<<<8192, 256>>>(out, n);           // ~1.07 GB store-bound
    router_kernel<<<G_ * T_, 256>>>(x, W, b);     // logits + softmax + z partials
    topk_kernel<<<G_ * E_, 1024>>>(out);          // 32 bitonic sorts + scatter
    zloss_kernel<<<1, 1>>>(out, n);               // scalar epilogue
}

// round 2
// speedup vs baseline: 1.0021x; 1.0021x over previous
#include <cuda_runtime.h>

#define G_ 4
#define T_ 2048
#define E_ 8
#define D_ 1024
#define C_ 2048

// probs scratch, expert-major: g_probs[(g*E + e)*T + t]
__device__ float g_probs[G_ * E_ * T_];
__device__ float g_zt[G_ * T_];           // per-token z-loss partial
__device__ float g_zsum;                  // reduced sum (written by topk)
__device__ int   g_tok [G_ * E_ * C_];    // rank table: token index or -1
__device__ float g_gate[G_ * E_ * C_];    // rank table: gate value

// ---------------------------------------------------------------------------
// Kernel 1: per-token router logits -> softmax probs + z-loss partial.
// One block per token (G*T blocks, 256 threads). Warp w handles expert w.
// ---------------------------------------------------------------------------
__global__ void router_kernel(const float* __restrict__ x,
                              const float* __restrict__ W,
                              const float* __restrict__ b) {
    int token = blockIdx.x;            // 0 .. G*T-1
    int g = token / T_;
    int t = token % T_;
    int warp = threadIdx.x >> 5;       // expert index (8 warps)
    int lane = threadIdx.x & 31;

    const float* xrow = x + (long long)token * D_;
    const float* wrow = W + warp * D_;

    float acc = 0.f;
    #pragma unroll 8
    for (int d = lane; d < D_; d += 32)
        acc += xrow[d] * wrow[d];
    #pragma unroll
    for (int o = 16; o > 0; o >>= 1)
        acc += __shfl_xor_sync(0xffffffffu, acc, o);

    __shared__ float logits[E_];
    if (lane == 0) logits[warp] = acc + b[warp];
    __syncthreads();

    if (threadIdx.x == 0) {
        float m = -1e30f;
        #pragma unroll
        for (int e = 0; e < E_; e++) m = fmaxf(m, logits[e]);
        float ex[E_];
        float s = 0.f;
        #pragma unroll
        for (int e = 0; e < E_; e++) { ex[e] = expf(logits[e] - m); s += ex[e]; }
        float inv = 1.f / s;
        float lse = m + logf(s);
        float zt = 0.f;
        #pragma unroll
        for (int e = 0; e < E_; e++) {
            g_probs[((g * E_) + e) * T_ + t] = ex[e] * inv;
            float ls = logits[e] - lse;
            zt += ls * ls;
        }
        g_zt[token] = zt;
    }
}

// ---------------------------------------------------------------------------
// Kernel 2: per-(g,e) top-cap via in-shared bitonic sort of packed keys
// (prob_bits << 32) | ~idx -> descending gives prob desc, idx asc on ties
// (matches jax.lax.top_k). Emits compact rank tables. Block 0 additionally
// reduces the z-loss partials (deterministic tree).
// ---------------------------------------------------------------------------
__global__ void topk_kernel() {
    __shared__ unsigned long long s[T_];   // 16 KB

    int ge = blockIdx.x;                   // 0..31
    int e = ge % E_;

    const float* p = g_probs + (long long)ge * T_;
    for (int t = threadIdx.x; t < T_; t += blockDim.x) {
        unsigned int pb = __float_as_uint(p[t]);   // probs > 0 -> bits monotonic
        s[t] = ((unsigned long long)pb << 32) | (unsigned int)(~t);
    }
    __syncthreads();

    for (int k = 2; k <= T_; k <<= 1) {
        for (int j = k >> 1; j > 0; j >>= 1) {
            for (int i = threadIdx.x; i < T_; i += blockDim.x) {
                int ixj = i ^ j;
                if (ixj > i) {
                    bool desc = ((i & k) == 0);
                    unsigned long long a = s[i], c = s[ixj];
                    if (desc ? (a < c) : (a > c)) { s[i] = c; s[ixj] = a; }
                }
            }
            __syncthreads();
        }
    }

    const int caps[E_] = {512, 512, 256, 256, 128, 128, 128, 128};
    int cap = caps[e];

    for (int r = threadIdx.x; r < C_; r += blockDim.x) {
        if (r < cap) {
            unsigned long long key = s[r];
            g_gate[ge * C_ + r] = __uint_as_float((unsigned int)(key >> 32));
            g_tok [ge * C_ + r] = (int)(~(unsigned int)(key & 0xffffffffu));
        } else {
            g_gate[ge * C_ + r] = 0.f;
            g_tok [ge * C_ + r] = -1;
        }
    }

    // Block 0: deterministic reduction of z-loss partials.
    if (blockIdx.x == 0) {
        __syncthreads();
        __shared__ float red[1024];
        float acc = 0.f;
        for (int i = threadIdx.x; i < G_ * T_; i += 1024)
            acc += g_zt[i];
        red[threadIdx.x] = acc;
        __syncthreads();
        for (int o = 512; o > 0; o >>= 1) {
            if (threadIdx.x < o) red[threadIdx.x] += red[threadIdx.x + o];
            __syncthreads();
        }
        if (threadIdx.x == 0) g_zsum = red[0];
    }
}

// ---------------------------------------------------------------------------
// Kernel 3: fused materialize — writes the entire 1.07 GB output in one pass.
// Block = (g, e, c-half, 8-token chunk). Each thread owns 4 consecutive c
// (one int4/float4 table slice in registers) and writes 8 rows of
// dispatch + combine via STG.128. Pure store-bandwidth.
// grid = G*E * 2 * (T/8) = 16384 blocks, 256 threads.
// ---------------------------------------------------------------------------
__global__ void materialize_kernel(float* __restrict__ out) {
    int B = blockIdx.x;
    int tch   = B & 255;          // token chunk: t in [tch*8, tch*8+8)
    int rest  = B >> 8;
    int chalf = rest & 1;         // which half of C
    int ge    = rest >> 1;        // 0..31
    int e = ge & 7;
    int g = ge >> 3;

    int c4 = chalf * 256 + threadIdx.x;          // float4 index along C: 0..511
    int4   tok4  = reinterpret_cast<const int4*  >(g_tok )[ge * (C_ / 4) + c4];
    float4 gate4 = reinterpret_cast<const float4*>(g_gate)[ge * (C_ / 4) + c4];

    const long long NTOT4 = (long long)G_ * T_ * E_ * (C_ / 4);
    float4* out4 = reinterpret_cast<float4*>(out);

    int tbase = tch * 8;
    #pragma unroll
    for (int i = 0; i < 8; i++) {
        int t = tbase + i;
        long long off = (((long long)g * T_ + t) * E_ + e) * (C_ / 4) + c4;
        float4 d, c;
        d.x = (tok4.x == t) ? 1.f : 0.f;  c.x = (tok4.x == t) ? gate4.x : 0.f;
        d.y = (tok4.y == t) ? 1.f : 0.f;  c.y = (tok4.y == t) ? gate4.y : 0.f;
        d.z = (tok4.z == t) ? 1.f : 0.f;  c.z = (tok4.z == t) ? gate4.z : 0.f;
        d.w = (tok4.w == t) ? 1.f : 0.f;  c.w = (tok4.w == t) ? gate4.w : 0.f;
        out4[off]         = d;   // dispatch_mask
        out4[off + NTOT4] = c;   // combine_array
    }

    if (B == 0 && threadIdx.x == 0)
        out[2 * (long long)G_ * T_ * E_ * C_] =
            g_zsum / (float)(G_ * T_ * E_);   // router_z_loss
}

extern "C" void kernel_launch(void* const* d_in, const int* in_sizes, int n_in,
                              void* d_out, int out_size) {
    const float* x = (const float*)d_in[0];   // token_inputs [G,T,D]
    const float* W = (const float*)d_in[1];   // [E,D]
    const float* b = (const float*)d_in[2];   // [E]
    float* out = (float*)d_out;

    router_kernel<<<G_ * T_, 256>>>(x, W, b);
    topk_kernel<<<G_ * E_, 1024>>>();
    materialize_kernel<<<G_ * E_ * 2 * (T_ / 8), 256>>>(out);
}

// round 3
// speedup vs baseline: 1.0393x; 1.0371x over previous
#include <cuda_runtime.h>

#define G_ 4
#define T_ 2048
#define E_ 8
#define D_ 1024
#define C_ 2048

// probs scratch, expert-major: g_probs[(g*E + e)*T + t]
__device__ float g_probs[G_ * E_ * T_];
__device__ float g_zt[G_ * T_];           // per-token z-loss partial
__device__ float g_zsum;                  // reduced sum (written by topk)
__device__ int   g_tok [G_ * E_ * C_];    // rank table: token index or -1
__device__ float g_gate[G_ * E_ * C_];    // rank table: gate value

// ---------------------------------------------------------------------------
// Kernel 1: router logits -> softmax probs + z-loss partial.
// 256 threads = 8 warps = 8 tokens per block. W staged in smem once.
// Each warp computes ALL 8 expert dots for its token: lane loads one float4
// of x (each x element read exactly once, coalesced) and FMAs against smem W.
// ---------------------------------------------------------------------------
__global__ void router_kernel(const float* __restrict__ x,
                              const float* __restrict__ W,
                              const float* __restrict__ b) {
    __shared__ float sW[E_ * D_];   // 32 KB
    __shared__ float sb[E_];

    for (int i = threadIdx.x; i < E_ * D_ / 4; i += blockDim.x)
        reinterpret_cast<float4*>(sW)[i] = reinterpret_cast<const float4*>(W)[i];
    if (threadIdx.x < E_) sb[threadIdx.x] = b[threadIdx.x];
    __syncthreads();

    int warp = threadIdx.x >> 5;
    int lane = threadIdx.x & 31;
    int token = blockIdx.x * 8 + warp;       // 0 .. G*T-1
    int g = token / T_;
    int t = token % T_;

    const float4* x4 = reinterpret_cast<const float4*>(x + (long long)token * D_);

    float acc[E_];
    #pragma unroll
    for (int e = 0; e < E_; e++) acc[e] = 0.f;

    #pragma unroll
    for (int i = 0; i < D_ / (32 * 4); i++) {      // 8 iterations
        int d4 = i * 32 + lane;
        float4 xv = x4[d4];
        #pragma unroll
        for (int e = 0; e < E_; e++) {
            float4 wv = reinterpret_cast<const float4*>(sW + e * D_)[d4];
            acc[e] += xv.x * wv.x + xv.y * wv.y + xv.z * wv.z + xv.w * wv.w;
        }
    }

    #pragma unroll
    for (int o = 16; o > 0; o >>= 1) {
        #pragma unroll
        for (int e = 0; e < E_; e++)
            acc[e] += __shfl_xor_sync(0xffffffffu, acc[e], o);
    }

    // every lane now holds all 8 logits
    float m = -1e30f;
    #pragma unroll
    for (int e = 0; e < E_; e++) { acc[e] += sb[e]; m = fmaxf(m, acc[e]); }
    float ex[E_];
    float s = 0.f;
    #pragma unroll
    for (int e = 0; e < E_; e++) { ex[e] = expf(acc[e] - m); s += ex[e]; }
    float inv = 1.f / s;
    float lse = m + logf(s);

    if (lane < E_)
        g_probs[(g * E_ + lane) * T_ + t] = ex[lane] * inv;
    if (lane == 0) {
        float zt = 0.f;
        #pragma unroll
        for (int e = 0; e < E_; e++) {
            float ls = acc[e] - lse;
            zt += ls * ls;
        }
        g_zt[token] = zt;
    }
}

// ---------------------------------------------------------------------------
// Kernel 2: per-(g,e) top-cap via in-shared bitonic sort of packed keys
// (prob_bits << 32) | ~idx -> descending gives prob desc, idx asc on ties
// (matches jax.lax.top_k). Emits compact rank tables. Block 0 additionally
// reduces the z-loss partials (deterministic tree).
// ---------------------------------------------------------------------------
__global__ void topk_kernel() {
    __shared__ unsigned long long s[T_];   // 16 KB

    int ge = blockIdx.x;                   // 0..31
    int e = ge % E_;

    const float* p = g_probs + (long long)ge * T_;
    for (int t = threadIdx.x; t < T_; t += blockDim.x) {
        unsigned int pb = __float_as_uint(p[t]);   // probs > 0 -> bits monotonic
        s[t] = ((unsigned long long)pb << 32) | (unsigned int)(~t);
    }
    __syncthreads();

    for (int k = 2; k <= T_; k <<= 1) {
        for (int j = k >> 1; j > 0; j >>= 1) {
            for (int i = threadIdx.x; i < T_; i += blockDim.x) {
                int ixj = i ^ j;
                if (ixj > i) {
                    bool desc = ((i & k) == 0);
                    unsigned long long a = s[i], c = s[ixj];
                    if (desc ? (a < c) : (a > c)) { s[i] = c; s[ixj] = a; }
                }
            }
            __syncthreads();
        }
    }

    const int caps[E_] = {512, 512, 256, 256, 128, 128, 128, 128};
    int cap = caps[e];

    for (int r = threadIdx.x; r < C_; r += blockDim.x) {
        if (r < cap) {
            unsigned long long key = s[r];
            g_gate[ge * C_ + r] = __uint_as_float((unsigned int)(key >> 32));
            g_tok [ge * C_ + r] = (int)(~(unsigned int)(key & 0xffffffffu));
        } else {
            g_gate[ge * C_ + r] = 0.f;
            g_tok [ge * C_ + r] = -1;
        }
    }

    // Block 0: deterministic reduction of z-loss partials.
    if (blockIdx.x == 0) {
        __syncthreads();
        __shared__ float red[1024];
        float acc = 0.f;
        for (int i = threadIdx.x; i < G_ * T_; i += 1024)
            acc += g_zt[i];
        red[threadIdx.x] = acc;
        __syncthreads();
        for (int o = 512; o > 0; o >>= 1) {
            if (threadIdx.x < o) red[threadIdx.x] += red[threadIdx.x + o];
            __syncthreads();
        }
        if (threadIdx.x == 0) g_zsum = red[0];
    }
}

// ---------------------------------------------------------------------------
// Kernel 3: fused materialize — writes the entire 1.07 GB output in one pass.
// Block = (g, e, c-half, 8-token chunk). Each thread owns 4 consecutive c
// (one int4/float4 table slice in registers) and writes 8 rows of
// dispatch + combine via STG.128. Pure store-bandwidth.
// ---------------------------------------------------------------------------
__global__ void materialize_kernel(float* __restrict__ out) {
    int B = blockIdx.x;
    int tch   = B & 255;          // token chunk: t in [tch*8, tch*8+8)
    int rest  = B >> 8;
    int chalf = rest & 1;         // which half of C
    int ge    = rest >> 1;        // 0..31
    int e = ge & 7;
    int g = ge >> 3;

    int c4 = chalf * 256 + threadIdx.x;          // float4 index along C: 0..511
    int4   tok4  = reinterpret_cast<const int4*  >(g_tok )[ge * (C_ / 4) + c4];
    float4 gate4 = reinterpret_cast<const float4*>(g_gate)[ge * (C_ / 4) + c4];

    const long long NTOT4 = (long long)G_ * T_ * E_ * (C_ / 4);
    float4* out4 = reinterpret_cast<float4*>(out);

    int tbase = tch * 8;
    #pragma unroll
    for (int i = 0; i < 8; i++) {
        int t = tbase + i;
        long long off = (((long long)g * T_ + t) * E_ + e) * (C_ / 4) + c4;
        float4 d, c;
        d.x = (tok4.x == t) ? 1.f : 0.f;  c.x = (tok4.x == t) ? gate4.x : 0.f;
        d.y = (tok4.y == t) ? 1.f : 0.f;  c.y = (tok4.y == t) ? gate4.y : 0.f;
        d.z = (tok4.z == t) ? 1.f : 0.f;  c.z = (tok4.z == t) ? gate4.z : 0.f;
        d.w = (tok4.w == t) ? 1.f : 0.f;  c.w = (tok4.w == t) ? gate4.w : 0.f;
        out4[off]         = d;   // dispatch_mask
        out4[off + NTOT4] = c;   // combine_array
    }

    if (B == 0 && threadIdx.x == 0)
        out[2 * (long long)G_ * T_ * E_ * C_] =
            g_zsum / (float)(G_ * T_ * E_);   // router_z_loss
}

extern "C" void kernel_launch(void* const* d_in, const int* in_sizes, int n_in,
                              void* d_out, int out_size) {
    const float* x = (const float*)d_in[0];   // token_inputs [G,T,D]
    const float* W = (const float*)d_in[1];   // [E,D]
    const float* b = (const float*)d_in[2];   // [E]
    float* out = (float*)d_out;

    router_kernel<<<G_ * T_ / 8, 256>>>(x, W, b);
    topk_kernel<<<G_ * E_, 1024>>>();
    materialize_kernel<<<G_ * E_ * 2 * (T_ / 8), 256>>>(out);
}